// round 8
// baseline (speedup 1.0000x reference)
#include <cuda_runtime.h>

// Geometry: (N=2, C=1, D=160, H=192, W=224), win=9, pad=4, zero-padded box sums.
#define NB   2
#define DD   160
#define HH   192
#define WW   224
#define HW   (HH * WW)            // 43008
#define DHW  (DD * HW)            // 6881280
#define VOLI (NB * DHW)           // 13762560
#define PAD  4
#define EPSV 1e-5f
#define SZ   ((size_t)VOLI)

#define CH     64                 // h-chunk per block in kA
#define NSTEPS (CH + 2 * PAD)     // 72
#define ROWL   (WW + 2 * PAD)     // 232

#define CHD  80                   // d-chunk per thread in k3
#define NCD  2
#define T3   (NB * NCD * HH * WW) // 172032
#define K3_BLOCKS (T3 / 256)      // 672

// Scratch: W+H box-summed fields. float4 = (sumI,sumJ,sumI2,sumJ2), float = sumIJ.
__device__ float4 g_B4[SZ];
__device__ float  g_B1[SZ];
__device__ double g_part[K3_BLOCKS];

// ---------------------------------------------------------------------------
// kA: fused W-pass + H-pass, software-pipelined.
//  - Row buffers hold (I,J) packed as float2 -> 9 LDS.64 taps instead of 18
//    LDS.32 (halves LSU instruction count in the hot loop).
//  - H-ring in smem, trimmed to 224 columns; total static smem ~44 KB so 5
//    blocks/SM fit (occupancy 62.5% vs 48.8%).
// ---------------------------------------------------------------------------
__global__ __launch_bounds__(256, 5) void kA(const float* __restrict__ I,
                                             const float* __restrict__ J) {
    __shared__ float4 ringQ[9][WW];     // 32,256 B : (v0,v1,v2,v3) history
    __shared__ float  ringS[9][WW];     //  8,064 B : v4 history
    __shared__ float2 sRow[2][ROWL];    //  3,712 B : packed (I,J) rows

    const int t = threadIdx.x;
    const int plane = blockIdx.x;              // n*DD + d
    const int h0 = blockIdx.y * CH;
    const float* Ip = I + (size_t)plane * HW;
    const float* Jp = J + (size_t)plane * HW;
    const size_t obase = (size_t)plane * HW;

    const int wld = t - PAD;                   // column this thread loads (halo)
    const bool lane_ok = (t < ROWL);
    const bool ld_ok = lane_ok && ((unsigned)wld < (unsigned)WW);

    // Zero-init ring (column-private; visibility via step-0 barrier).
    if (t < WW) {
#pragma unroll
        for (int s = 0; s < 9; s++) {
            ringQ[s][t] = make_float4(0.f, 0.f, 0.f, 0.f);
            ringS[s][t] = 0.f;
        }
    }

    float S0 = 0.f, S1 = 0.f, S2 = 0.f, S3 = 0.f, S4 = 0.f;

    // Prefetch step 0 (row h0 - PAD)
    float vi = 0.f, vj = 0.f;
    {
        const int hh = h0 - PAD;
        if (ld_ok && (unsigned)hh < (unsigned)HH) {
            const size_t p = (size_t)hh * WW + wld;
            vi = Ip[p]; vj = Jp[p];
        }
    }

    int rs = 0;                                // ring slot = step % 9
#pragma unroll 2
    for (int step = 0; step < NSTEPS; step++) {
        const int buf = step & 1;

        // publish prefetched row
        if (lane_ok) sRow[buf][t] = make_float2(vi, vj);

        // prefetch next row (independent of smem/compute)
        {
            const int hh = h0 - PAD + step + 1;
            vi = 0.f; vj = 0.f;
            if (ld_ok && (unsigned)hh < (unsigned)HH) {
                const size_t p = (size_t)hh * WW + wld;
                vi = Ip[p]; vj = Jp[p];
            }
        }

        __syncthreads();

        if (t < WW) {
            float v0 = 0.f, v1 = 0.f, v2 = 0.f, v3 = 0.f, v4 = 0.f;
#pragma unroll
            for (int q = 0; q < 9; q++) {
                const float2 ab = sRow[buf][t + q];
                v0 += ab.x; v1 += ab.y;
                v2 += ab.x * ab.x; v3 += ab.y * ab.y; v4 += ab.x * ab.y;
            }
            // H sliding window via smem ring (own column only)
            const float4 o4 = ringQ[rs][t];
            const float  o1 = ringS[rs][t];
            S0 += v0 - o4.x;
            S1 += v1 - o4.y;
            S2 += v2 - o4.z;
            S3 += v3 - o4.w;
            S4 += v4 - o1;
            ringQ[rs][t] = make_float4(v0, v1, v2, v3);
            ringS[rs][t] = v4;

            if (step >= 2 * PAD) {
                const int ho = h0 + step - 2 * PAD;
                const size_t idx = obase + (size_t)ho * WW + t;
                g_B4[idx] = make_float4(S0, S1, S2, S3);
                g_B1[idx] = S4;
            }
        }
        rs = (rs == 8) ? 0 : rs + 1;
        // no second sync: next step's barrier separates row-buffer reuse
    }
}

// ---------------------------------------------------------------------------
// k3: D-axis sliding box sum fused with NCC pointwise loss + block reduction.
// Thread = (n, d-chunk, h, w). Coalesced along w; float4 + float loads.
// launch_bounds(256,6) caps regs (~42) -> 48 warps/SM instead of 32.
// ---------------------------------------------------------------------------
__global__ __launch_bounds__(256, 6) void k3_dpass() {
    const int t = blockIdx.x * blockDim.x + threadIdx.x;
    float local = 0.f;

    if (t < T3) {
        int w = t % WW;
        int r = t / WW;
        int h = r % HH; r /= HH;
        int chunk = r & (NCD - 1);
        int n = r >> 1;
        int d0 = chunk * CHD;
        size_t base = (size_t)n * DHW + (size_t)h * WW + w;

        float S0 = 0.f, S1 = 0.f, S2 = 0.f, S3 = 0.f, S4 = 0.f;
#pragma unroll
        for (int k = -PAD; k <= PAD; k++) {
            int dd = d0 + k;
            if ((unsigned)dd < (unsigned)DD) {
                size_t p = base + (size_t)dd * HW;
                float4 f = g_B4[p];
                S0 += f.x; S1 += f.y; S2 += f.z; S3 += f.w;
                S4 += g_B1[p];
            }
        }

        const float ws = 729.f, inv_ws = 1.f / 729.f;

#pragma unroll 2
        for (int d = d0; d < d0 + CHD; d++) {
            float ui = S0 * inv_ws;
            float uj = S1 * inv_ws;
            float cross = S4 - uj * S0 - ui * S1 + ui * uj * ws;
            float iv = fmaxf(S2 - 2.f * ui * S0 + ui * ui * ws, EPSV);
            float jv = fmaxf(S3 - 2.f * uj * S1 + uj * uj * ws, EPSV);
            local += (cross * cross) / (iv * jv);

            int da = d + PAD + 1;
            int ds = d - PAD;
            if ((unsigned)da < (unsigned)DD) {
                size_t q = base + (size_t)da * HW;
                float4 f = g_B4[q];
                S0 += f.x; S1 += f.y; S2 += f.z; S3 += f.w;
                S4 += g_B1[q];
            }
            if ((unsigned)ds < (unsigned)DD) {
                size_t q = base + (size_t)ds * HW;
                float4 f = g_B4[q];
                S0 -= f.x; S1 -= f.y; S2 -= f.z; S3 -= f.w;
                S4 -= g_B1[q];
            }
        }
    }

#pragma unroll
    for (int o = 16; o > 0; o >>= 1)
        local += __shfl_down_sync(0xffffffffu, local, o);

    __shared__ float wsum[8];
    if ((threadIdx.x & 31) == 0) wsum[threadIdx.x >> 5] = local;
    __syncthreads();
    if (threadIdx.x == 0) {
        float s = 0.f;
#pragma unroll
        for (int i = 0; i < 8; i++) s += wsum[i];
        g_part[blockIdx.x] = (double)s;
    }
}

// ---------------------------------------------------------------------------
// Final: parallel deterministic reduction of 672 partials.
// ---------------------------------------------------------------------------
__global__ __launch_bounds__(256) void k_final(float* __restrict__ out) {
    __shared__ double sd[256];
    const int t = threadIdx.x;
    double s = 0.0;
    for (int i = t; i < K3_BLOCKS; i += 256) s += g_part[i];
    sd[t] = s;
    __syncthreads();
#pragma unroll
    for (int o = 128; o > 0; o >>= 1) {
        if (t < o) sd[t] += sd[t + o];
        __syncthreads();
    }
    if (t == 0) out[0] = (float)(-sd[0] / (double)VOLI);
}

extern "C" void kernel_launch(void* const* d_in, const int* in_sizes, int n_in,
                              void* d_out, int out_size) {
    const float* I = (const float*)d_in[0];   // y_true
    const float* J = (const float*)d_in[1];   // y_pred

    dim3 gridA(NB * DD, HH / CH);             // (320, 3)
    kA<<<gridA, 256>>>(I, J);
    k3_dpass<<<K3_BLOCKS, 256>>>();
    k_final<<<1, 256>>>((float*)d_out);
}